// round 2
// baseline (speedup 1.0000x reference)
#include <cuda_runtime.h>
#include <cstdint>

#define Tdim 128
#define Sdim 2048
#define Bdim 8
#define LPAD 132            // padded smem leading dim (float), multiple of 4

// 8 MB transposed weight scratch: g_Wt[p][q][t] = W[t][p][q]
__device__ float g_Wt[Tdim * Tdim * Tdim];
__device__ float g_base[Tdim];

typedef unsigned long long ull;

__device__ __forceinline__ ull pack2(float lo, float hi) {
    ull r;
    asm("mov.b64 %0, {%1, %2};" : "=l"(r)
        : "r"(__float_as_uint(lo)), "r"(__float_as_uint(hi)));
    return r;
}
__device__ __forceinline__ void fma2(ull& c, ull a, ull b) {
    asm("fma.rn.f32x2 %0, %1, %2, %0;" : "+l"(c) : "l"(a), "l"(b));
}
__device__ __forceinline__ ull mul2(ull a, ull b) {
    ull r;
    asm("mul.rn.f32x2 %0, %1, %2;" : "=l"(r) : "l"(a), "l"(b));
    return r;
}
__device__ __forceinline__ float lo32(ull v) { return __uint_as_float((unsigned)(v & 0xffffffffULL)); }
__device__ __forceinline__ float hi32(ull v) { return __uint_as_float((unsigned)(v >> 32)); }

// ---------------------------------------------------------------------------
// prep: g_base[t] = (sum_j w_red[j]) * tanh(b_comp[t]) + b_red[0]
// ---------------------------------------------------------------------------
__global__ void prep_kernel(const float* __restrict__ b_comp,
                            const float* __restrict__ w_red,
                            const float* __restrict__ b_red) {
    __shared__ float red[128];
    float s = 0.0f;
    for (int j = threadIdx.x; j < Sdim; j += 128) s += w_red[j];
    red[threadIdx.x] = s;
    __syncthreads();
    for (int off = 64; off > 0; off >>= 1) {
        if (threadIdx.x < off) red[threadIdx.x] += red[threadIdx.x + off];
        __syncthreads();
    }
    float wsum = red[0];
    g_base[threadIdx.x] = wsum * tanhf(b_comp[threadIdx.x]) + b_red[0];
}

// ---------------------------------------------------------------------------
// fill: out[b,i,t] = g_base[t]   (2M floats, as float4)
// ---------------------------------------------------------------------------
__global__ void fill_kernel(float4* __restrict__ out4) {
    int i = blockIdx.x * 256 + threadIdx.x;      // 524288 float4 total
    int t4 = (i & 31) << 2;
    out4[i] = make_float4(g_base[t4], g_base[t4 + 1], g_base[t4 + 2], g_base[t4 + 3]);
}

// ---------------------------------------------------------------------------
// transpose: g_Wt[p][q][t] = W[t][p][q].  grid (4,4,128), block (32,8)
// ---------------------------------------------------------------------------
__global__ void transpose_kernel(const float* __restrict__ W) {
    __shared__ float tile[32][33];
    const int p  = blockIdx.z;
    const int q0 = blockIdx.x * 32;
    const int t0 = blockIdx.y * 32;
    for (int r = threadIdx.y; r < 32; r += 8)
        tile[r][threadIdx.x] =
            W[(size_t)(t0 + r) * (Tdim * Tdim) + p * Tdim + (q0 + threadIdx.x)];
    __syncthreads();
    for (int r = threadIdx.y; r < 32; r += 8)
        g_Wt[(size_t)p * (Tdim * Tdim) + (size_t)(q0 + r) * Tdim + (t0 + threadIdx.x)] =
            tile[threadIdx.x][r];
}

// ---------------------------------------------------------------------------
// main: per 128-token tile, C[tok][t] = sum_{p,q} Tk[tok][p]*H[tok][q]*Wt[p][q][t]
// then act = tanh(C + b_comp); atomicAdd w[j]*(act - tanh(b_comp)) into head row.
// f32x2 packed FMA, accumulators pack token pairs.
// ---------------------------------------------------------------------------
__global__ __launch_bounds__(256, 1) void main_kernel(
    const float* __restrict__ token,
    const int*   __restrict__ heads,
    const float* __restrict__ b_comp,
    const float* __restrict__ w_red,
    float*       __restrict__ out) {
    extern __shared__ float smem[];
    float* sTkT = smem;                    // [p][tok]  128 x LPAD
    float* sHT  = smem + Tdim * LPAD;      // [q][tok]  128 x LPAD
    float* sB   = smem + 2 * Tdim * LPAD;  // [32][128] W chunk

    const int tid  = threadIdx.x;
    const int tok0 = blockIdx.x * 128;

    // load token tile, store transposed, compute H = tanh(token) transposed
    const float4* gT = (const float4*)(token + (size_t)tok0 * Tdim);
    for (int i = tid; i < Tdim * Tdim / 4; i += 256) {
        float4 v = gT[i];
        int tok = i >> 5;            // 32 float4 per token row
        int p4  = (i & 31) << 2;
        sTkT[(p4 + 0) * LPAD + tok] = v.x;
        sTkT[(p4 + 1) * LPAD + tok] = v.y;
        sTkT[(p4 + 2) * LPAD + tok] = v.z;
        sTkT[(p4 + 3) * LPAD + tok] = v.w;
        sHT[(p4 + 0) * LPAD + tok] = tanhf(v.x);
        sHT[(p4 + 1) * LPAD + tok] = tanhf(v.y);
        sHT[(p4 + 2) * LPAD + tok] = tanhf(v.z);
        sHT[(p4 + 3) * LPAD + tok] = tanhf(v.w);
    }
    __syncthreads();

    const int ty   = tid >> 4;
    const int tx   = tid & 15;
    const int trow = ty << 3;   // 8 tokens (4 packed pairs)
    const int tcol = tx << 3;   // 8 output t columns

    ull c2[4][8];
#pragma unroll
    for (int i = 0; i < 4; i++)
#pragma unroll
        for (int j = 0; j < 8; j++) c2[i][j] = 0ULL;

    for (int p = 0; p < Tdim; ++p) {
        ull s2[4];
        {
            ulonglong2 u0 = *(const ulonglong2*)&sTkT[p * LPAD + trow];
            ulonglong2 u1 = *(const ulonglong2*)&sTkT[p * LPAD + trow + 4];
            s2[0] = u0.x; s2[1] = u0.y; s2[2] = u1.x; s2[3] = u1.y;
        }
        const float4* Wp = (const float4*)(g_Wt + (size_t)p * (Tdim * Tdim));
        for (int qc = 0; qc < Tdim; qc += 32) {
            __syncthreads();   // previous chunk fully consumed
#pragma unroll 4
            for (int i = tid; i < 32 * 32; i += 256)
                ((float4*)sB)[i] = Wp[qc * 32 + i];
            __syncthreads();
#pragma unroll 4
            for (int q = 0; q < 32; ++q) {
                ulonglong2 h01 = *(const ulonglong2*)&sHT[(qc + q) * LPAD + trow];
                ulonglong2 h23 = *(const ulonglong2*)&sHT[(qc + q) * LPAD + trow + 4];
                ull a2[4];
                a2[0] = mul2(s2[0], h01.x);
                a2[1] = mul2(s2[1], h01.y);
                a2[2] = mul2(s2[2], h23.x);
                a2[3] = mul2(s2[3], h23.y);
                float4 b0 = *(const float4*)&sB[q * Tdim + tcol];
                float4 b1 = *(const float4*)&sB[q * Tdim + tcol + 4];
                ull bd[8];
                bd[0] = pack2(b0.x, b0.x); bd[1] = pack2(b0.y, b0.y);
                bd[2] = pack2(b0.z, b0.z); bd[3] = pack2(b0.w, b0.w);
                bd[4] = pack2(b1.x, b1.x); bd[5] = pack2(b1.y, b1.y);
                bd[6] = pack2(b1.z, b1.z); bd[7] = pack2(b1.w, b1.w);
#pragma unroll
                for (int i = 0; i < 4; i++)
#pragma unroll
                    for (int j = 0; j < 8; j++) fma2(c2[i][j], a2[i], bd[j]);
            }
        }
    }

    // epilogue: act = tanh(C + b_comp); scatter delta into head rows
    const int bIdx = tok0 >> 11;          // S = 2048
    const int seq0 = tok0 & (Sdim - 1);
    float bc[8], bv[8];
#pragma unroll
    for (int j = 0; j < 8; j++) {
        bc[j] = b_comp[tcol + j];
        bv[j] = tanhf(bc[j]);
    }
#pragma unroll
    for (int ip = 0; ip < 4; ++ip) {
#pragma unroll
        for (int half = 0; half < 2; ++half) {
            int tok  = trow + 2 * ip + half;
            int jseq = seq0 + tok;
            float wj = w_red[jseq];
            int head = heads[(size_t)bIdx * Sdim + jseq];
            float* orow = out + ((size_t)bIdx * Sdim + head) * Tdim + tcol;
#pragma unroll
            for (int j = 0; j < 8; j++) {
                float v   = half ? hi32(c2[ip][j]) : lo32(c2[ip][j]);
                float act = tanhf(v + bc[j]);
                atomicAdd(orow + j, wj * (act - bv[j]));
            }
        }
    }
}

// ---------------------------------------------------------------------------
extern "C" void kernel_launch(void* const* d_in, const int* in_sizes, int n_in,
                              void* d_out, int out_size) {
    const float* token  = (const float*)d_in[0];
    // d_in[1] = dep_embeddings: dead input (source bug), unused
    const int*   heads  = (const int*)d_in[2];
    const float* W      = (const float*)d_in[3];
    const float* b_comp = (const float*)d_in[4];
    const float* w_red  = (const float*)d_in[5];
    const float* b_red  = (const float*)d_in[6];
    float* out = (float*)d_out;

    prep_kernel<<<1, 128>>>(b_comp, w_red, b_red);
    fill_kernel<<<(Bdim * Sdim * Tdim / 4) / 256, 256>>>((float4*)out);

    dim3 tg(4, 4, 128);
    transpose_kernel<<<tg, dim3(32, 8)>>>(W);

    const int smem_bytes = (2 * Tdim * LPAD + 32 * Tdim) * (int)sizeof(float);
    cudaFuncSetAttribute(main_kernel, cudaFuncAttributeMaxDynamicSharedMemorySize,
                         smem_bytes);
    main_kernel<<<Bdim * Sdim / 128, 256, smem_bytes>>>(token, heads, b_comp, w_red, out);
}

// round 6
// speedup vs baseline: 2.9117x; 2.9117x over previous
#include <cuda_runtime.h>
#include <cuda_bf16.h>
#include <cstdint>

#define TT   128
#define SEQ  2048
#define NTOK 16384

// ---------------- device scratch ----------------
__device__ __align__(1024) __nv_bfloat16 g_Whi[TT * TT * TT];   // [t][p][q]
__device__ __align__(1024) __nv_bfloat16 g_Wlo[TT * TT * TT];   // [t][p][q]
__device__ __align__(1024) float         g_tokT[TT * NTOK];     // [p][tok]
__device__ float g_base[TT];

// ---------------- smem layout (bytes) ----------------
#define PITCH   272                 // 128 bf16 (256B) + 16B pad: conflict-free ldmatrix
#define BMAT    (128 * PITCH)       // 34816: one 128x128 bf16 matrix
#define BSTAGE  (2 * BMAT)          // hi + lo
#define BC_OFF  (2 * BSTAGE)        // 139264
#define BV_OFF  (BC_OFF + 512)
#define SMEM_SZ (BV_OFF + 512)      // 140288

__device__ __forceinline__ uint32_t s2u(const void* p) {
    uint32_t a;
    asm("{ .reg .u64 t; cvta.to.shared.u64 t, %1; cvt.u32.u64 %0, t; }"
        : "=r"(a) : "l"(p));
    return a;
}
__device__ __forceinline__ void ldsm4(uint32_t* r, uint32_t a) {
    asm volatile("ldmatrix.sync.aligned.m8n8.x4.shared.b16 {%0,%1,%2,%3}, [%4];"
                 : "=r"(r[0]), "=r"(r[1]), "=r"(r[2]), "=r"(r[3]) : "r"(a));
}
__device__ __forceinline__ void mma16816(float* d, const uint32_t* a,
                                         const uint32_t* b, const float* c) {
    asm volatile(
        "mma.sync.aligned.m16n8k16.row.col.f32.bf16.bf16.f32 "
        "{%0,%1,%2,%3}, {%4,%5,%6,%7}, {%8,%9}, {%10,%11,%12,%13};"
        : "=f"(d[0]), "=f"(d[1]), "=f"(d[2]), "=f"(d[3])
        : "r"(a[0]), "r"(a[1]), "r"(a[2]), "r"(a[3]), "r"(b[0]), "r"(b[1]),
          "f"(c[0]), "f"(c[1]), "f"(c[2]), "f"(c[3]));
}
#define CP_COMMIT() asm volatile("cp.async.commit_group;" ::: "memory")
#define CP_WAIT(n)  asm volatile("cp.async.wait_group %0;" :: "n"(n) : "memory")

// load B_p (hi+lo, 128 t-rows x 128 q bf16 each) into stage s; 16 cp.async/thread
__device__ __forceinline__ void load_B(uint32_t sb, int p, int s, int tid) {
#pragma unroll
    for (int it = 0; it < 16; ++it) {
        int item = tid + it * 256;             // 0..4095
        int mat  = item >> 11;                 // 0=hi 1=lo
        int rem  = item & 2047;
        int row  = rem >> 4;                   // t
        int seg  = rem & 15;                   // 16B segment
        const __nv_bfloat16* src =
            (mat ? g_Wlo : g_Whi) + ((size_t)(row * TT + p)) * TT + seg * 8;
        uint32_t dst = sb + s * BSTAGE + mat * BMAT + row * PITCH + seg * 16;
        asm volatile("cp.async.cg.shared.global [%0], [%1], 16;"
                     :: "r"(dst), "l"(src) : "memory");
    }
}

// ---------------------------------------------------------------------------
__global__ void prep_kernel(const float* __restrict__ b_comp,
                            const float* __restrict__ w_red,
                            const float* __restrict__ b_red) {
    __shared__ float red[128];
    float s = 0.0f;
    for (int j = threadIdx.x; j < SEQ; j += 128) s += w_red[j];
    red[threadIdx.x] = s;
    __syncthreads();
    for (int off = 64; off > 0; off >>= 1) {
        if (threadIdx.x < off) red[threadIdx.x] += red[threadIdx.x + off];
        __syncthreads();
    }
    g_base[threadIdx.x] = red[0] * tanhf(b_comp[threadIdx.x]) + b_red[0];
}

__global__ void fill_kernel(float4* __restrict__ out4) {
    int i = blockIdx.x * 256 + threadIdx.x;
    int t4 = (i & 31) << 2;
    out4[i] = make_float4(g_base[t4], g_base[t4 + 1], g_base[t4 + 2], g_base[t4 + 3]);
}

__global__ void wsplit_kernel(const float* __restrict__ W) {
    int i = blockIdx.x * 256 + threadIdx.x;
    float w = W[i];
    __nv_bfloat16 hi = __float2bfloat16(w);
    g_Whi[i] = hi;
    g_Wlo[i] = __float2bfloat16(w - __bfloat162float(hi));
}

__global__ void tokT_kernel(const float* __restrict__ token) {
    __shared__ float tile[32][33];
    const int t0 = blockIdx.x * 32;
    const int p0 = blockIdx.y * 32;
    for (int r = threadIdx.y; r < 32; r += 8)
        tile[r][threadIdx.x] = token[(size_t)(t0 + r) * TT + p0 + threadIdx.x];
    __syncthreads();
    for (int r = threadIdx.y; r < 32; r += 8)
        g_tokT[(size_t)(p0 + r) * NTOK + t0 + threadIdx.x] = tile[threadIdx.x][r];
}

// ---------------------------------------------------------------------------
__global__ __launch_bounds__(256, 1) void main_kernel(
    const float* __restrict__ token,
    const int*   __restrict__ heads,
    const float* __restrict__ b_comp,
    const float* __restrict__ w_red,
    float*       __restrict__ out) {
    extern __shared__ char smem[];
    const uint32_t sb = s2u(smem);
    const int tid  = threadIdx.x;
    const int wid  = tid >> 5;
    const int lane = tid & 31;
    const int g    = lane >> 2;
    const int tig  = lane & 3;
    const int m0   = wid * 16;                 // warp's 16 token rows
    const int tok0 = blockIdx.x * 128;

    // ---- prologue: stage h = tanh(token) hi/lo into stage-0 region ----
    const float4* tk4 = (const float4*)(token + (size_t)tok0 * TT);
    for (int i = tid; i < 128 * 32; i += 256) {
        float4 v = tk4[i];
        int tok = i >> 5;
        int q4  = (i & 31) << 2;
        float h[4] = { tanhf(v.x), tanhf(v.y), tanhf(v.z), tanhf(v.w) };
        uint16_t hi[4], lo[4];
#pragma unroll
        for (int e = 0; e < 4; e++) {
            __nv_bfloat16 hb = __float2bfloat16(h[e]);
            __nv_bfloat16 lb = __float2bfloat16(h[e] - __bfloat162float(hb));
            hi[e] = *(uint16_t*)&hb;
            lo[e] = *(uint16_t*)&lb;
        }
        uint2 hv, lv;
        hv.x = ((uint32_t)hi[1] << 16) | hi[0];
        hv.y = ((uint32_t)hi[3] << 16) | hi[2];
        lv.x = ((uint32_t)lo[1] << 16) | lo[0];
        lv.y = ((uint32_t)lo[3] << 16) | lo[2];
        *(uint2*)(smem + 0    + tok * PITCH + q4 * 2) = hv;
        *(uint2*)(smem + BMAT + tok * PITCH + q4 * 2) = lv;
    }
    if (tid < 128) {
        float bc = b_comp[tid];
        ((float*)(smem + BC_OFF))[tid] = bc;
        ((float*)(smem + BV_OFF))[tid] = tanhf(bc);
    }
    __syncthreads();

    // ---- A fragments, persistent in registers (h is p-invariant) ----
    uint32_t ahi[8][4], alo[8][4];
    {
        const int arow = m0 + (lane & 7) + ((lane >> 3) & 1) * 8;
        const int acol = (lane >> 4) * 16;
#pragma unroll
        for (int kk = 0; kk < 8; ++kk) {
            ldsm4(ahi[kk], sb + 0    + arow * PITCH + kk * 32 + acol);
            ldsm4(alo[kk], sb + BMAT + arow * PITCH + kk * 32 + acol);
        }
    }
    __syncthreads();   // stage-0 region may now be overwritten by B

    float val[64];
#pragma unroll
    for (int j = 0; j < 64; j++) val[j] = 0.0f;
    const float z4[4] = {0.f, 0.f, 0.f, 0.f};

    load_B(sb, 0, 0, tid); CP_COMMIT();
    load_B(sb, 1, 1, tid); CP_COMMIT();

    const uint32_t brow_off = (lane & 7) * PITCH + (lane >> 3) * 16;

    for (int p = 0; p < 128; ++p) {
        const int s = p & 1;
        if (p < 126) CP_WAIT(1); else CP_WAIT(0);
        __syncthreads();

        const float tkL = g_tokT[(size_t)p * NTOK + tok0 + m0 + g];
        const float tkH = g_tokT[(size_t)p * NTOK + tok0 + m0 + 8 + g];
        const uint32_t bs = sb + s * BSTAGE;

#pragma unroll 4
        for (int nt = 0; nt < 16; ++nt) {
            float u[4];
            const uint32_t bbase = bs + nt * (8 * PITCH) + brow_off;
#pragma unroll
            for (int kk2 = 0; kk2 < 4; ++kk2) {
                const int kk = kk2 * 2;
                uint32_t bh[4], bl[4];
                ldsm4(bh, bbase + kk * 32);
                ldsm4(bl, bbase + kk * 32 + BMAT);
                mma16816(u, ahi[kk], bh + 0, kk2 ? u : z4);
                mma16816(u, ahi[kk], bl + 0, u);
                mma16816(u, alo[kk], bh + 0, u);
                mma16816(u, ahi[kk + 1], bh + 2, u);
                mma16816(u, ahi[kk + 1], bl + 2, u);
                mma16816(u, alo[kk + 1], bh + 2, u);
            }
            val[nt * 4 + 0] = fmaf(tkL, u[0], val[nt * 4 + 0]);
            val[nt * 4 + 1] = fmaf(tkL, u[1], val[nt * 4 + 1]);
            val[nt * 4 + 2] = fmaf(tkH, u[2], val[nt * 4 + 2]);
            val[nt * 4 + 3] = fmaf(tkH, u[3], val[nt * 4 + 3]);
        }
        __syncthreads();
        if (p + 2 < 128) { load_B(sb, p + 2, s, tid); CP_COMMIT(); }
    }

    // ---- epilogue: tanh + scatter-add into head rows ----
    const float* sBc = (const float*)(smem + BC_OFF);
    const float* sBv = (const float*)(smem + BV_OFF);
#pragma unroll
    for (int half = 0; half < 2; ++half) {
        const int gtok = tok0 + m0 + half * 8 + g;
        const int bI   = gtok >> 11;
        const int jseq = gtok & (SEQ - 1);
        const float ww = w_red[jseq];
        const int head = heads[gtok];
        float* orow = out + ((size_t)(bI * SEQ + head)) * TT;
        const int vo = half * 2;     // regs 0,1 = lower row; 2,3 = upper row
#pragma unroll
        for (int nt = 0; nt < 16; ++nt) {
            const int c = nt * 8 + 2 * tig;
            float a0 = tanhf(val[nt * 4 + vo + 0] + sBc[c]);
            float a1 = tanhf(val[nt * 4 + vo + 1] + sBc[c + 1]);
            atomicAdd(orow + c,     ww * (a0 - sBv[c]));
            atomicAdd(orow + c + 1, ww * (a1 - sBv[c + 1]));
        }
    }
}

// ---------------------------------------------------------------------------
extern "C" void kernel_launch(void* const* d_in, const int* in_sizes, int n_in,
                              void* d_out, int out_size) {
    const float* token  = (const float*)d_in[0];
    const int*   heads  = (const int*)d_in[2];
    const float* W      = (const float*)d_in[3];
    const float* b_comp = (const float*)d_in[4];
    const float* w_red  = (const float*)d_in[5];
    const float* b_red  = (const float*)d_in[6];
    float* out = (float*)d_out;

    prep_kernel<<<1, 128>>>(b_comp, w_red, b_red);
    fill_kernel<<<(NTOK * TT / 4) / 256, 256>>>((float4*)out);
    wsplit_kernel<<<(TT * TT * TT) / 256, 256>>>(W);
    tokT_kernel<<<dim3(NTOK / 32, TT / 32), dim3(32, 8)>>>(token);

    cudaFuncSetAttribute(main_kernel, cudaFuncAttributeMaxDynamicSharedMemorySize,
                         SMEM_SZ);
    main_kernel<<<NTOK / 128, 256, SMEM_SZ>>>(token, heads, b_comp, w_red, out);
}

// round 8
// speedup vs baseline: 4.3047x; 1.4784x over previous
#include <cuda_runtime.h>
#include <cuda_fp16.h>
#include <cstdint>

#define TT   128
#define SEQ  2048
#define NTOK 16384

// ---------------- device scratch ----------------
__device__ __align__(1024) __half g_Wh[TT * TT * TT];     // [t][p][q] fp16
__device__ __align__(1024) float  g_tokT[TT * NTOK];      // [p][tok]
__device__ float g_base[TT];

// ---------------- smem layout (bytes) ----------------
#define PITCH   272                 // 128 fp16 (256B) + 16B pad
#define BMAT    (128 * PITCH)       // 34816: one 128x128 fp16 matrix
#define NSTAGE  4
#define BC_OFF  (NSTAGE * BMAT)     // 139264
#define BV_OFF  (BC_OFF + 512)
#define SMEM_SZ (BV_OFF + 512)      // 140288

__device__ __forceinline__ uint32_t s2u(const void* p) {
    uint32_t a;
    asm("{ .reg .u64 t; cvta.to.shared.u64 t, %1; cvt.u32.u64 %0, t; }"
        : "=r"(a) : "l"(p));
    return a;
}
__device__ __forceinline__ void ldsm4(uint32_t* r, uint32_t a) {
    asm volatile("ldmatrix.sync.aligned.m8n8.x4.shared.b16 {%0,%1,%2,%3}, [%4];"
                 : "=r"(r[0]), "=r"(r[1]), "=r"(r[2]), "=r"(r[3]) : "r"(a));
}
__device__ __forceinline__ void mma16816(float* d, const uint32_t* a,
                                         const uint32_t* b, const float* c) {
    asm volatile(
        "mma.sync.aligned.m16n8k16.row.col.f32.f16.f16.f32 "
        "{%0,%1,%2,%3}, {%4,%5,%6,%7}, {%8,%9}, {%10,%11,%12,%13};"
        : "=f"(d[0]), "=f"(d[1]), "=f"(d[2]), "=f"(d[3])
        : "r"(a[0]), "r"(a[1]), "r"(a[2]), "r"(a[3]), "r"(b[0]), "r"(b[1]),
          "f"(c[0]), "f"(c[1]), "f"(c[2]), "f"(c[3]));
}
#define CP_COMMIT() asm volatile("cp.async.commit_group;" ::: "memory")
#define CP_WAIT(n)  asm volatile("cp.async.wait_group %0;" :: "n"(n) : "memory")

// load B_p (128 t-rows x 128 q fp16) into stage s; 8 cp.async per thread
__device__ __forceinline__ void load_B(uint32_t sb, int p, int s, int tid) {
#pragma unroll
    for (int it = 0; it < 8; ++it) {
        int item = tid + it * 256;             // 0..2047
        int row  = item >> 4;                  // t
        int seg  = item & 15;                  // 16B segment
        const __half* src = g_Wh + ((size_t)(row * TT + p)) * TT + seg * 8;
        uint32_t dst = sb + s * BMAT + row * PITCH + seg * 16;
        asm volatile("cp.async.cg.shared.global [%0], [%1], 16;"
                     :: "r"(dst), "l"(src) : "memory");
    }
}

// ---------------------------------------------------------------------------
__global__ void prep_kernel(const float* __restrict__ b_comp,
                            const float* __restrict__ w_red,
                            const float* __restrict__ b_red) {
    __shared__ float red[128];
    float s = 0.0f;
    for (int j = threadIdx.x; j < SEQ; j += 128) s += w_red[j];
    red[threadIdx.x] = s;
    __syncthreads();
    for (int off = 64; off > 0; off >>= 1) {
        if (threadIdx.x < off) red[threadIdx.x] += red[threadIdx.x + off];
        __syncthreads();
    }
    g_base[threadIdx.x] = red[0] * tanhf(b_comp[threadIdx.x]) + b_red[0];
}

__global__ void fill_kernel(float4* __restrict__ out4) {
    int i = blockIdx.x * 256 + threadIdx.x;
    int t4 = (i & 31) << 2;
    out4[i] = make_float4(g_base[t4], g_base[t4 + 1], g_base[t4 + 2], g_base[t4 + 3]);
}

__global__ void wsplit_kernel(const float* __restrict__ W) {
    int i = blockIdx.x * 256 + threadIdx.x;
    g_Wh[i] = __float2half_rn(W[i]);
}

__global__ void tokT_kernel(const float* __restrict__ token) {
    __shared__ float tile[32][33];
    const int t0 = blockIdx.x * 32;
    const int p0 = blockIdx.y * 32;
    for (int r = threadIdx.y; r < 32; r += 8)
        tile[r][threadIdx.x] = token[(size_t)(t0 + r) * TT + p0 + threadIdx.x];
    __syncthreads();
    for (int r = threadIdx.y; r < 32; r += 8)
        g_tokT[(size_t)(p0 + r) * NTOK + t0 + threadIdx.x] = tile[threadIdx.x][r];
}

// ---------------------------------------------------------------------------
__global__ __launch_bounds__(256, 1) void main_kernel(
    const float* __restrict__ token,
    const int*   __restrict__ heads,
    const float* __restrict__ b_comp,
    const float* __restrict__ w_red,
    float*       __restrict__ out) {
    extern __shared__ char smem[];
    const uint32_t sb = s2u(smem);
    const int tid  = threadIdx.x;
    const int wid  = tid >> 5;
    const int lane = tid & 31;
    const int g    = lane >> 2;
    const int tig  = lane & 3;
    const int m0   = wid * 16;                 // warp's 16 token rows
    const int tok0 = blockIdx.x * 128;

    // ---- prologue: h = tanh(token), fp16 hi/lo staged in stages 0/1 ----
    const float4* tk4 = (const float4*)(token + (size_t)tok0 * TT);
    for (int i = tid; i < 128 * 32; i += 256) {
        float4 v = tk4[i];
        int tok = i >> 5;
        int q4  = (i & 31) << 2;
        float h[4] = { tanhf(v.x), tanhf(v.y), tanhf(v.z), tanhf(v.w) };
        uint16_t hi[4], lo[4];
#pragma unroll
        for (int e = 0; e < 4; e++) {
            __half hb = __float2half_rn(h[e]);
            __half lb = __float2half_rn(h[e] - __half2float(hb));
            hi[e] = *(uint16_t*)&hb;
            lo[e] = *(uint16_t*)&lb;
        }
        uint2 hv, lv;
        hv.x = ((uint32_t)hi[1] << 16) | hi[0];
        hv.y = ((uint32_t)hi[3] << 16) | hi[2];
        lv.x = ((uint32_t)lo[1] << 16) | lo[0];
        lv.y = ((uint32_t)lo[3] << 16) | lo[2];
        *(uint2*)(smem + 0    + tok * PITCH + q4 * 2) = hv;
        *(uint2*)(smem + BMAT + tok * PITCH + q4 * 2) = lv;
    }
    if (tid < 128) {
        float bc = b_comp[tid];
        ((float*)(smem + BC_OFF))[tid] = bc;
        ((float*)(smem + BV_OFF))[tid] = tanhf(bc);
    }
    __syncthreads();

    // ---- A fragments, persistent in registers (h is p-invariant) ----
    uint32_t ahi[8][4], alo[8][4];
    {
        const int arow = m0 + (lane & 7) + ((lane >> 3) & 1) * 8;
        const int acol = (lane >> 4) * 16;
#pragma unroll
        for (int kk = 0; kk < 8; ++kk) {
            ldsm4(ahi[kk], sb + 0    + arow * PITCH + kk * 32 + acol);
            ldsm4(alo[kk], sb + BMAT + arow * PITCH + kk * 32 + acol);
        }
    }
    __syncthreads();   // stages 0/1 may now be overwritten by B

    float val[64];
#pragma unroll
    for (int j = 0; j < 64; j++) val[j] = 0.0f;
    const float z4[4] = {0.f, 0.f, 0.f, 0.f};

    // prime 3 stages
    load_B(sb, 0, 0, tid); CP_COMMIT();
    load_B(sb, 1, 1, tid); CP_COMMIT();
    load_B(sb, 2, 2, tid); CP_COMMIT();

    const uint32_t brow_off = (lane & 7) * PITCH + (lane >> 3) * 16;

    for (int p = 0; p < 128; ++p) {
        const int s = p & 3;
        CP_WAIT(2);            // group p complete (p+1, p+2 may be in flight)
        __syncthreads();       // also guards stage (p+3)%4 reuse (read at p-1)

        const float tkL = g_tokT[(size_t)p * NTOK + tok0 + m0 + g];
        const float tkH = g_tokT[(size_t)p * NTOK + tok0 + m0 + 8 + g];
        const uint32_t bs = sb + s * BMAT;

#pragma unroll 4
        for (int nt = 0; nt < 16; ++nt) {
            float u[4];
            const uint32_t bbase = bs + nt * (8 * PITCH) + brow_off;
#pragma unroll
            for (int kk2 = 0; kk2 < 4; ++kk2) {
                const int kk = kk2 * 2;
                uint32_t b[4];
                ldsm4(b, bbase + kk2 * 64);
                mma16816(u, ahi[kk],     b + 0, kk2 ? u : z4);
                mma16816(u, alo[kk],     b + 0, u);
                mma16816(u, ahi[kk + 1], b + 2, u);
                mma16816(u, alo[kk + 1], b + 2, u);
            }
            val[nt * 4 + 0] = fmaf(tkL, u[0], val[nt * 4 + 0]);
            val[nt * 4 + 1] = fmaf(tkL, u[1], val[nt * 4 + 1]);
            val[nt * 4 + 2] = fmaf(tkH, u[2], val[nt * 4 + 2]);
            val[nt * 4 + 3] = fmaf(tkH, u[3], val[nt * 4 + 3]);
        }
        if (p + 3 < 128) { load_B(sb, p + 3, (p + 3) & 3, tid); CP_COMMIT(); }
    }

    // ---- epilogue: tanh + scatter-add into head rows ----
    const float* sBc = (const float*)(smem + BC_OFF);
    const float* sBv = (const float*)(smem + BV_OFF);
#pragma unroll
    for (int half = 0; half < 2; ++half) {
        const int gtok = tok0 + m0 + half * 8 + g;
        const int bI   = gtok >> 11;
        const int jseq = gtok & (SEQ - 1);
        const float ww = w_red[jseq];
        const int head = heads[gtok];
        float* orow = out + ((size_t)(bI * SEQ + head)) * TT;
        const int vo = half * 2;     // regs 0,1 = lower row; 2,3 = upper row
#pragma unroll
        for (int nt = 0; nt < 16; ++nt) {
            const int c = nt * 8 + 2 * tig;
            float a0 = tanhf(val[nt * 4 + vo + 0] + sBc[c]);
            float a1 = tanhf(val[nt * 4 + vo + 1] + sBc[c + 1]);
            atomicAdd(orow + c,     ww * (a0 - sBv[c]));
            atomicAdd(orow + c + 1, ww * (a1 - sBv[c + 1]));
        }
    }
}

// ---------------------------------------------------------------------------
extern "C" void kernel_launch(void* const* d_in, const int* in_sizes, int n_in,
                              void* d_out, int out_size) {
    const float* token  = (const float*)d_in[0];
    const int*   heads  = (const int*)d_in[2];
    const float* W      = (const float*)d_in[3];
    const float* b_comp = (const float*)d_in[4];
    const float* w_red  = (const float*)d_in[5];
    const float* b_red  = (const float*)d_in[6];
    float* out = (float*)d_out;

    prep_kernel<<<1, 128>>>(b_comp, w_red, b_red);
    fill_kernel<<<(NTOK * TT / 4) / 256, 256>>>((float4*)out);
    wsplit_kernel<<<(TT * TT * TT) / 256, 256>>>(W);
    tokT_kernel<<<dim3(NTOK / 32, TT / 32), dim3(32, 8)>>>(token);

    cudaFuncSetAttribute(main_kernel, cudaFuncAttributeMaxDynamicSharedMemorySize,
                         SMEM_SZ);
    main_kernel<<<NTOK / 128, 256, SMEM_SZ>>>(token, heads, b_comp, w_red, out);
}

// round 11
// speedup vs baseline: 4.7459x; 1.1025x over previous
#include <cuda_runtime.h>
#include <cuda_fp16.h>
#include <cstdint>

#define TT   128
#define SEQ  2048
#define NTOK 16384

// ---------------- device scratch ----------------
__device__ __align__(1024) __half g_Wh[TT * TT * TT];     // [t][p][q] fp16
__device__ __align__(1024) float  g_tokT[TT * NTOK];      // [p][tok]
__device__ float g_base[TT];

// ---------------- smem layout (bytes) ----------------
#define PITCH   272                 // 128 fp16 (256B) + 16B pad
#define BMAT    (128 * PITCH)       // 34816: one 128x128 fp16 matrix
#define NSTAGE  4
#define BC_OFF  (NSTAGE * BMAT)     // 139264
#define BV_OFF  (BC_OFF + 512)
#define SMEM_SZ (BV_OFF + 512)      // 140288

__device__ __forceinline__ uint32_t s2u(const void* p) {
    uint32_t a;
    asm("{ .reg .u64 t; cvta.to.shared.u64 t, %1; cvt.u32.u64 %0, t; }"
        : "=r"(a) : "l"(p));
    return a;
}
__device__ __forceinline__ void ldsm4(uint32_t* r, uint32_t a) {
    asm volatile("ldmatrix.sync.aligned.m8n8.x4.shared.b16 {%0,%1,%2,%3}, [%4];"
                 : "=r"(r[0]), "=r"(r[1]), "=r"(r[2]), "=r"(r[3]) : "r"(a));
}
__device__ __forceinline__ void mma16816(float* d, const uint32_t* a,
                                         const uint32_t* b, const float* c) {
    asm volatile(
        "mma.sync.aligned.m16n8k16.row.col.f32.f16.f16.f32 "
        "{%0,%1,%2,%3}, {%4,%5,%6,%7}, {%8,%9}, {%10,%11,%12,%13};"
        : "=f"(d[0]), "=f"(d[1]), "=f"(d[2]), "=f"(d[3])
        : "r"(a[0]), "r"(a[1]), "r"(a[2]), "r"(a[3]), "r"(b[0]), "r"(b[1]),
          "f"(c[0]), "f"(c[1]), "f"(c[2]), "f"(c[3]));
}
#define CP_COMMIT() asm volatile("cp.async.commit_group;" ::: "memory")
#define CP_WAIT(n)  asm volatile("cp.async.wait_group %0;" :: "n"(n) : "memory")

// load B_p (128 t-rows x 128 q fp16) into stage s; 8 cp.async per thread
__device__ __forceinline__ void load_B(uint32_t sb, int p, int s, int tid) {
#pragma unroll
    for (int it = 0; it < 8; ++it) {
        int item = tid + it * 256;             // 0..2047
        int row  = item >> 4;                  // t
        int seg  = item & 15;                  // 16B segment
        const __half* src = g_Wh + ((size_t)(row * TT + p)) * TT + seg * 8;
        uint32_t dst = sb + s * BMAT + row * PITCH + seg * 16;
        asm volatile("cp.async.cg.shared.global [%0], [%1], 16;"
                     :: "r"(dst), "l"(src) : "memory");
    }
}

// ---------------------------------------------------------------------------
__global__ void prep_kernel(const float* __restrict__ b_comp,
                            const float* __restrict__ w_red,
                            const float* __restrict__ b_red) {
    __shared__ float red[128];
    float s = 0.0f;
    for (int j = threadIdx.x; j < SEQ; j += 128) s += w_red[j];
    red[threadIdx.x] = s;
    __syncthreads();
    for (int off = 64; off > 0; off >>= 1) {
        if (threadIdx.x < off) red[threadIdx.x] += red[threadIdx.x + off];
        __syncthreads();
    }
    g_base[threadIdx.x] = red[0] * tanhf(b_comp[threadIdx.x]) + b_red[0];
}

__global__ void fill_kernel(float4* __restrict__ out4) {
    int i = blockIdx.x * 256 + threadIdx.x;
    int t4 = (i & 31) << 2;
    out4[i] = make_float4(g_base[t4], g_base[t4 + 1], g_base[t4 + 2], g_base[t4 + 3]);
}

__global__ void wsplit_kernel(const float* __restrict__ W) {
    int i = blockIdx.x * 256 + threadIdx.x;
    g_Wh[i] = __float2half_rn(W[i]);
}

__global__ void tokT_kernel(const float* __restrict__ token) {
    __shared__ float tile[32][33];
    const int t0 = blockIdx.x * 32;
    const int p0 = blockIdx.y * 32;
    for (int r = threadIdx.y; r < 32; r += 8)
        tile[r][threadIdx.x] = token[(size_t)(t0 + r) * TT + p0 + threadIdx.x];
    __syncthreads();
    for (int r = threadIdx.y; r < 32; r += 8)
        g_tokT[(size_t)(p0 + r) * NTOK + t0 + threadIdx.x] = tile[threadIdx.x][r];
}

// ---------------------------------------------------------------------------
__global__ __launch_bounds__(256, 1) void main_kernel(
    const float* __restrict__ token,
    const int*   __restrict__ heads,
    const float* __restrict__ b_comp,
    const float* __restrict__ w_red,
    float*       __restrict__ out) {
    extern __shared__ char smem[];
    const uint32_t sb = s2u(smem);
    const int tid  = threadIdx.x;
    const int wid  = tid >> 5;
    const int lane = tid & 31;
    const int g    = lane >> 2;
    const int tig  = lane & 3;
    const int mg   = wid & 3;                  // 4 m-groups
    const int ng   = wid >> 2;                 // 2 n-groups
    const int m0   = mg * 32;                  // warp's 32 token rows
    const int n0   = ng * 64;                  // warp's 64 output cols
    const int tok0 = blockIdx.x * 128;

    // ---- prologue: h = tanh(token) fp16, staged in stage 0 ----
    const float4* tk4 = (const float4*)(token + (size_t)tok0 * TT);
    for (int i = tid; i < 128 * 32; i += 256) {
        float4 v = tk4[i];
        int tok = i >> 5;
        int q4  = (i & 31) << 2;
        __half h0 = __float2half_rn(tanhf(v.x));
        __half h1 = __float2half_rn(tanhf(v.y));
        __half h2 = __float2half_rn(tanhf(v.z));
        __half h3 = __float2half_rn(tanhf(v.w));
        uint2 hv;
        hv.x = ((uint32_t)*(uint16_t*)&h1 << 16) | *(uint16_t*)&h0;
        hv.y = ((uint32_t)*(uint16_t*)&h3 << 16) | *(uint16_t*)&h2;
        *(uint2*)(smem + tok * PITCH + q4 * 2) = hv;
    }
    if (tid < 128) {
        float bc = b_comp[tid];
        ((float*)(smem + BC_OFF))[tid] = bc;
        ((float*)(smem + BV_OFF))[tid] = tanhf(bc);
    }
    __syncthreads();

    // ---- A fragments (2 m16 tiles), persistent in registers ----
    uint32_t a[2][8][4];
    {
        const int aro  = (lane & 7) + ((lane >> 3) & 1) * 8;
        const int acol = (lane >> 4) * 16;
#pragma unroll
        for (int mt = 0; mt < 2; ++mt)
#pragma unroll
            for (int kk = 0; kk < 8; ++kk)
                ldsm4(a[mt][kk], sb + (m0 + mt * 16 + aro) * PITCH + kk * 32 + acol);
    }
    __syncthreads();   // stage 0 may now be overwritten by B

    float val[2][32];
#pragma unroll
    for (int mt = 0; mt < 2; ++mt)
#pragma unroll
        for (int j = 0; j < 32; j++) val[mt][j] = 0.0f;
    const float z4[4] = {0.f, 0.f, 0.f, 0.f};

    // prime 3 stages
    load_B(sb, 0, 0, tid); CP_COMMIT();
    load_B(sb, 1, 1, tid); CP_COMMIT();
    load_B(sb, 2, 2, tid); CP_COMMIT();

    const uint32_t brow_off = (n0 + (lane & 7)) * PITCH + (lane >> 3) * 16;

    for (int p = 0; p < 128; ++p) {
        const int s = p & 3;
        CP_WAIT(2);            // group p complete
        __syncthreads();       // also guards stage (p+3)%4 reuse (read at p-1)

        const float* tkp = g_tokT + (size_t)p * NTOK + tok0 + m0;
        const float tk0L = tkp[g],      tk0H = tkp[8 + g];
        const float tk1L = tkp[16 + g], tk1H = tkp[24 + g];
        const uint32_t bs = sb + s * BMAT;

#pragma unroll 4
        for (int nt = 0; nt < 8; ++nt) {
            float u0[4], u1[4];
            const uint32_t bbase = bs + nt * (8 * PITCH) + brow_off;
#pragma unroll
            for (int kk2 = 0; kk2 < 4; ++kk2) {
                const int kk = kk2 * 2;
                uint32_t b[4];
                ldsm4(b, bbase + kk2 * 64);
                mma16816(u0, a[0][kk],     b + 0, kk2 ? u0 : z4);
                mma16816(u1, a[1][kk],     b + 0, kk2 ? u1 : z4);
                mma16816(u0, a[0][kk + 1], b + 2, u0);
                mma16816(u1, a[1][kk + 1], b + 2, u1);
            }
            val[0][nt * 4 + 0] = fmaf(tk0L, u0[0], val[0][nt * 4 + 0]);
            val[0][nt * 4 + 1] = fmaf(tk0L, u0[1], val[0][nt * 4 + 1]);
            val[0][nt * 4 + 2] = fmaf(tk0H, u0[2], val[0][nt * 4 + 2]);
            val[0][nt * 4 + 3] = fmaf(tk0H, u0[3], val[0][nt * 4 + 3]);
            val[1][nt * 4 + 0] = fmaf(tk1L, u1[0], val[1][nt * 4 + 0]);
            val[1][nt * 4 + 1] = fmaf(tk1L, u1[1], val[1][nt * 4 + 1]);
            val[1][nt * 4 + 2] = fmaf(tk1H, u1[2], val[1][nt * 4 + 2]);
            val[1][nt * 4 + 3] = fmaf(tk1H, u1[3], val[1][nt * 4 + 3]);
        }
        if (p + 3 < 128) { load_B(sb, p + 3, (p + 3) & 3, tid); CP_COMMIT(); }
    }

    // ---- epilogue: tanh + scatter-add into head rows ----
    const float* sBc = (const float*)(smem + BC_OFF);
    const float* sBv = (const float*)(smem + BV_OFF);
#pragma unroll
    for (int mt = 0; mt < 2; ++mt) {
#pragma unroll
        for (int half = 0; half < 2; ++half) {
            const int gtok = tok0 + m0 + mt * 16 + half * 8 + g;
            const int bI   = gtok >> 11;
            const int jseq = gtok & (SEQ - 1);
            const float ww = w_red[jseq];
            const int head = heads[gtok];
            float* orow = out + ((size_t)(bI * SEQ + head)) * TT;
            const int vo = half * 2;
#pragma unroll
            for (int nt = 0; nt < 8; ++nt) {
                const int c = n0 + nt * 8 + 2 * tig;
                float a0 = tanhf(val[mt][nt * 4 + vo + 0] + sBc[c]);
                float a1 = tanhf(val[mt][nt * 4 + vo + 1] + sBc[c + 1]);
                atomicAdd(orow + c,     ww * (a0 - sBv[c]));
                atomicAdd(orow + c + 1, ww * (a1 - sBv[c + 1]));
            }
        }
    }
}

// ---------------------------------------------------------------------------
extern "C" void kernel_launch(void* const* d_in, const int* in_sizes, int n_in,
                              void* d_out, int out_size) {
    const float* token  = (const float*)d_in[0];
    const int*   heads  = (const int*)d_in[2];
    const float* W      = (const float*)d_in[3];
    const float* b_comp = (const float*)d_in[4];
    const float* w_red  = (const float*)d_in[5];
    const float* b_red  = (const float*)d_in[6];
    float* out = (float*)d_out;

    prep_kernel<<<1, 128>>>(b_comp, w_red, b_red);
    fill_kernel<<<(NTOK * TT / 4) / 256, 256>>>((float4*)out);
    wsplit_kernel<<<(TT * TT * TT) / 256, 256>>>(W);
    tokT_kernel<<<dim3(NTOK / 32, TT / 32), dim3(32, 8)>>>(token);

    cudaFuncSetAttribute(main_kernel, cudaFuncAttributeMaxDynamicSharedMemorySize,
                         SMEM_SZ);
    main_kernel<<<NTOK / 128, 256, SMEM_SZ>>>(token, heads, b_comp, w_red, out);
}